// round 3
// baseline (speedup 1.0000x reference)
#include <cuda_runtime.h>
#include <cstdint>
#include <cstddef>

#define TPB   256
#define NKEY  127
#define NH    4
#define DK    64
#define DOUT  256
#define STR   68   // padded row stride (floats): consecutive rows are 4 banks apart

static constexpr int KV_FLOATS = 128 * STR;
static constexpr int WK_FLOATS = DOUT * STR;
static constexpr int OFF_KV0  = 0;
static constexpr int OFF_KV1  = OFF_KV0 + KV_FLOATS;
static constexpr int OFF_WK   = OFF_KV1 + KV_FLOATS;
static constexpr int OFF_QB   = OFF_WK + WK_FLOATS;
static constexpr int OFF_Q    = OFF_QB + DOUT;
static constexpr int OFF_WS   = OFF_Q + DK;
static constexpr int OFF_BIAS = OFF_WS + DK;
static constexpr int OFF_SC   = OFF_BIAS + DK;          // [4][128]
static constexpr int OFF_W    = OFF_SC + NH * 128;      // [128][4] n-major!
static constexpr int OFF_WV   = OFF_W + 128 * NH;       // [256]
static constexpr int OFF_PART = OFF_WV + DOUT;          // [256][4]
static constexpr int OFF_BS   = OFF_PART + DOUT * 4;
static constexpr int SMEM_FLOATS = OFF_BS + 4;
static constexpr int SMEM_BYTES  = SMEM_FLOATS * 4;

__device__ __forceinline__ float tanh_fast(float x) {
    float y;
    asm("tanh.approx.f32 %0, %1;" : "=f"(y) : "f"(x));
    return y;
}
__device__ __forceinline__ unsigned long long fma2(unsigned long long a,
                                                   unsigned long long b,
                                                   unsigned long long c) {
    unsigned long long d;
    asm("fma.rn.f32x2 %0, %1, %2, %3;" : "=l"(d) : "l"(a), "l"(b), "l"(c));
    return d;
}

#define CP_ASYNC16(sdst, gsrc)                                                \
    asm volatile("cp.async.cg.shared.global [%0], [%1], 16;"                  \
                 :: "r"(sdst), "l"(gsrc))
#define CP_COMMIT() asm volatile("cp.async.commit_group;")
#define CP_WAIT1()  asm volatile("cp.async.wait_group 1;")

__device__ __forceinline__ void prefetch_kv(const float* __restrict__ gsrc,
                                            float* sdst) {
    #pragma unroll 2
    for (int j = threadIdx.x; j < NKEY * 16; j += TPB) {
        int row = j >> 4;
        int c4  = j & 15;
        unsigned sa =
            (unsigned)__cvta_generic_to_shared(sdst + row * STR + c4 * 4);
        CP_ASYNC16(sa, gsrc + j * 4);
    }
}

__global__ void __launch_bounds__(TPB, 1)
raamh_kernel(const float* __restrict__ q_x, const float* __restrict__ kv_x,
             const float* __restrict__ Wk,  const float* __restrict__ Wq,
             const float* __restrict__ Wv,  const float* __restrict__ bias,
             const float* __restrict__ Ws,  const float* __restrict__ bs,
             float* __restrict__ out, int BT)
{
    extern __shared__ float smem[];
    float* s_kv[2] = { smem + OFF_KV0, smem + OFF_KV1 };
    float* s_wk   = smem + OFF_WK;
    float* s_qb   = smem + OFF_QB;
    float* s_q    = smem + OFF_Q;
    float* s_ws   = smem + OFF_WS;
    float* s_bias = smem + OFF_BIAS;
    float* s_sc   = smem + OFF_SC;
    float* s_w    = smem + OFF_W;     // [n][4] heads, n-major
    float* s_wv   = smem + OFF_WV;
    float* s_part = smem + OFF_PART;  // [h*64+i][4] quarters
    float* s_bs   = smem + OFF_BS;

    const int tid  = threadIdx.x;
    const int lane = tid & 31;
    const int wrp  = tid >> 5;
    const int ng   = lane & 3;        // 4 n-lanes
    const int og   = lane >> 2;       // 8 o-lanes
    const int nb   = wrp & 3;         // n-block (32 n each)
    const int hb   = wrp >> 2;        // head-pair (o 0..127 / 128..255)
    const int h    = tid >> 6;
    const int lg   = tid & 63;

    // ---- one-time staging ----
    {
        const float4* wk4 = (const float4*)Wk;
        #pragma unroll 4
        for (int j = tid; j < DOUT * 16; j += TPB) {
            int row = j >> 4, c4 = j & 15;
            float4 v = wk4[j];
            *(float4*)(s_wk + row * STR + c4 * 4) = v;
        }
        if (tid < DK) {
            s_ws[tid]   = Ws[tid];
            s_bias[tid] = bias[tid];
        }
        if (tid == 0) s_bs[0] = bs[0];
        if (tid < 128) {  // zero garbage row 127 of both kv buffers
            s_kv[tid >> 6][127 * STR + (tid & 63)] = 0.f;
        }
    }

    int bt0 = blockIdx.x;
    int buf = 0;
    prefetch_kv(kv_x + (size_t)bt0 * (NKEY * DK), s_kv[0]);
    CP_COMMIT();

    for (int bt = bt0; bt < BT; bt += gridDim.x) {
        if (tid < DK) s_q[tid] = q_x[bt * DK + tid];

        int bt_next = bt + gridDim.x;
        if (bt_next < BT)
            prefetch_kv(kv_x + (size_t)bt_next * (NKEY * DK), s_kv[buf ^ 1]);
        CP_COMMIT();
        CP_WAIT1();
        __syncthreads();

        const float* kvb = s_kv[buf];

        // ---- q projection + bias ----
        {
            const float4* wq4 = (const float4*)(Wq + tid * DK);
            float a0 = 0.f, a1 = 0.f, a2 = 0.f, a3 = 0.f;
            #pragma unroll
            for (int i = 0; i < 16; i++) {
                float4 w = __ldg(wq4 + i);
                a0 = fmaf(s_q[4 * i + 0], w.x, a0);
                a1 = fmaf(s_q[4 * i + 1], w.y, a1);
                a2 = fmaf(s_q[4 * i + 2], w.z, a2);
                a3 = fmaf(s_q[4 * i + 3], w.w, a3);
            }
            s_qb[tid] = (a0 + a1) + (a2 + a3) + s_bias[tid & (DK - 1)];
        }
        __syncthreads();

        const float bsv = s_bs[0];

        // ---- score GEMM: 8n x 16o per thread, one pass (8 warps) ----
        {
            const float* kvp = kvb  + (nb * 32 + ng) * STR;  // rows +4j
            const float* wkp = s_wk + (hb * 128 + og) * STR; // rows +8oi

            unsigned long long acc[8][16];
            #pragma unroll
            for (int j = 0; j < 8; ++j)
                #pragma unroll
                for (int oi = 0; oi < 16; ++oi) acc[j][oi] = 0ull;

            #pragma unroll 1
            for (int kk = 0; kk < DK; kk += 4) {
                ulonglong2 kvv[8];
                #pragma unroll
                for (int j = 0; j < 8; ++j)
                    kvv[j] = *(const ulonglong2*)(kvp + j * 4 * STR + kk);
                #pragma unroll
                for (int oi = 0; oi < 16; ++oi) {
                    ulonglong2 w =
                        *(const ulonglong2*)(wkp + oi * 8 * STR + kk);
                    #pragma unroll
                    for (int j = 0; j < 8; ++j) {
                        acc[j][oi] = fma2(kvv[j].x, w.x, acc[j][oi]);
                        acc[j][oi] = fma2(kvv[j].y, w.y, acc[j][oi]);
                    }
                }
            }

            // epilogue: tanh + Ws reduction; o = hb*128 + oi*8 + og
            float part[2][8];
            #pragma unroll
            for (int hh = 0; hh < 2; ++hh)
                #pragma unroll
                for (int j = 0; j < 8; ++j) part[hh][j] = 0.f;

            #pragma unroll
            for (int oi = 0; oi < 16; ++oi) {
                const int hh  = oi >> 3;
                const int kih = (oi & 7) * 8 + og;      // k within head
                float wsk = s_ws[kih];
                float qbo = s_qb[(hb * 2 + hh) * 64 + kih];
                #pragma unroll
                for (int j = 0; j < 8; ++j) {
                    float lo, hi;
                    asm("mov.b64 {%0, %1}, %2;"
                        : "=f"(lo), "=f"(hi) : "l"(acc[j][oi]));
                    part[hh][j] =
                        fmaf(wsk, tanh_fast(lo + hi + qbo), part[hh][j]);
                }
            }
            #pragma unroll
            for (int m = 4; m <= 16; m <<= 1)
                #pragma unroll
                for (int hh = 0; hh < 2; ++hh)
                    #pragma unroll
                    for (int j = 0; j < 8; ++j)
                        part[hh][j] +=
                            __shfl_xor_sync(0xffffffffu, part[hh][j], m);
            if (og == 0) {
                #pragma unroll
                for (int hh = 0; hh < 2; ++hh)
                    #pragma unroll
                    for (int j = 0; j < 8; ++j)
                        s_sc[(hb * 2 + hh) * 128 + nb * 32 + j * 4 + ng] =
                            part[hh][j] + bsv;
            }
        }
        __syncthreads();

        // ---- softmax per head (one warp per head), write n-major s_w ----
        if (tid < NH * 32) {
            int hh = tid >> 5;
            int ln = tid & 31;
            const float* sc = s_sc + hh * 128;
            float v0 = sc[ln];
            float v1 = sc[ln + 32];
            float v2 = sc[ln + 64];
            float v3 = (ln + 96 < NKEY) ? sc[ln + 96] : -1e30f;
            float m = fmaxf(fmaxf(v0, v1), fmaxf(v2, v3));
            #pragma unroll
            for (int o = 16; o > 0; o >>= 1)
                m = fmaxf(m, __shfl_xor_sync(0xffffffffu, m, o));
            float e0 = __expf(v0 - m);
            float e1 = __expf(v1 - m);
            float e2 = __expf(v2 - m);
            float e3 = (ln + 96 < NKEY) ? __expf(v3 - m) : 0.f;
            float s = (e0 + e1) + (e2 + e3);
            #pragma unroll
            for (int o = 16; o > 0; o >>= 1)
                s += __shfl_xor_sync(0xffffffffu, s, o);
            float inv = 1.f / s;
            s_w[ln * 4 + hh]        = e0 * inv;
            s_w[(ln + 32) * 4 + hh] = e1 * inv;
            s_w[(ln + 64) * 4 + hh] = e2 * inv;
            if (ln + 96 < NKEY) s_w[(ln + 96) * 4 + hh] = e3 * inv;
        }
        __syncthreads();

        // ---- weighted kv sum, quarter-split over n ----
        {
            const int q4 = tid >> 6;           // n-quarter
            const int i  = tid & 63;           // column
            float a0 = 0.f, a1 = 0.f, a2 = 0.f, a3 = 0.f;
            const int n0 = q4 * 32;
            const int n1 = (q4 == 3) ? NKEY : n0 + 32;
            #pragma unroll 4
            for (int n = n0; n < n1; ++n) {
                float  v  = kvb[n * STR + i];
                float4 w4 = *(const float4*)(s_w + n * 4);
                a0 = fmaf(w4.x, v, a0);
                a1 = fmaf(w4.y, v, a1);
                a2 = fmaf(w4.z, v, a2);
                a3 = fmaf(w4.w, v, a3);
            }
            s_part[(0 * 64 + i) * 4 + q4] = a0;
            s_part[(1 * 64 + i) * 4 + q4] = a1;
            s_part[(2 * 64 + i) * 4 + q4] = a2;
            s_part[(3 * 64 + i) * 4 + q4] = a3;
        }
        __syncthreads();
        {
            float4 p = *(const float4*)(s_part + tid * 4);
            s_wv[tid] = (p.x + p.y) + (p.z + p.w);
        }
        __syncthreads();

        // ---- output projection ----
        {
            const float* wvh = s_wv + (h << 6);
            const float4* wv4 = (const float4*)(Wv + tid * DK);
            float a0 = 0.f, a1 = 0.f, a2 = 0.f, a3 = 0.f;
            #pragma unroll
            for (int i = 0; i < 16; i++) {
                float4 w = __ldg(wv4 + i);
                a0 = fmaf(wvh[4 * i + 0], w.x, a0);
                a1 = fmaf(wvh[4 * i + 1], w.y, a1);
                a2 = fmaf(wvh[4 * i + 2], w.z, a2);
                a3 = fmaf(wvh[4 * i + 3], w.w, a3);
            }
            out[(size_t)bt * DOUT + tid] = (a0 + a1) + (a2 + a3);
        }

        buf ^= 1;
    }
}

extern "C" void kernel_launch(void* const* d_in, const int* in_sizes, int n_in,
                              void* d_out, int out_size) {
    (void)n_in; (void)out_size;
    const float* q_x  = (const float*)d_in[0];
    const float* kv_x = (const float*)d_in[1];
    const float* Wk   = (const float*)d_in[2];
    const float* Wq   = (const float*)d_in[3];
    const float* Wv   = (const float*)d_in[4];
    const float* bias = (const float*)d_in[5];
    const float* Ws   = (const float*)d_in[6];
    const float* bs   = (const float*)d_in[7];
    float* out = (float*)d_out;

    const int BT = in_sizes[0] / DK;          // b*t
    int grid = BT < 152 ? BT : 152;

    cudaFuncSetAttribute(raamh_kernel,
                         cudaFuncAttributeMaxDynamicSharedMemorySize,
                         SMEM_BYTES);
    raamh_kernel<<<grid, TPB, SMEM_BYTES>>>(q_x, kv_x, Wk, Wq, Wv,
                                            bias, Ws, bs, out, BT);
}

// round 4
// speedup vs baseline: 1.8487x; 1.8487x over previous
#include <cuda_runtime.h>
#include <cstdint>
#include <cstddef>

#define TPB   256
#define NKEY  127
#define NH    4
#define DK    64
#define DOUT  256
#define STR   68   // padded row stride (floats); 17 16B-units -> conflict-free

static constexpr int KV_FLOATS = 128 * STR;
static constexpr int WK_FLOATS = DOUT * STR;
static constexpr int OFF_KV0  = 0;
static constexpr int OFF_KV1  = OFF_KV0 + KV_FLOATS;
static constexpr int OFF_WK   = OFF_KV1 + KV_FLOATS;
static constexpr int OFF_QB   = OFF_WK + WK_FLOATS;
static constexpr int OFF_Q    = OFF_QB + DOUT;
static constexpr int OFF_WS   = OFF_Q + DK;
static constexpr int OFF_BIAS = OFF_WS + DK;
static constexpr int OFF_SC   = OFF_BIAS + DK;          // [4][128]
static constexpr int OFF_W    = OFF_SC + NH * 128;      // [128][4] n-major
static constexpr int OFF_WV   = OFF_W + 128 * NH;       // [256]
static constexpr int OFF_PART = OFF_WV + DOUT;          // [256][4]
static constexpr int OFF_BS   = OFF_PART + DOUT * 4;
static constexpr int SMEM_FLOATS = OFF_BS + 4;
static constexpr int SMEM_BYTES  = SMEM_FLOATS * 4;

__device__ __forceinline__ float tanh_fast(float x) {
    float y;
    asm("tanh.approx.f32 %0, %1;" : "=f"(y) : "f"(x));
    return y;
}
__device__ __forceinline__ unsigned long long fma2(unsigned long long a,
                                                   unsigned long long b,
                                                   unsigned long long c) {
    unsigned long long d;
    asm("fma.rn.f32x2 %0, %1, %2, %3;" : "=l"(d) : "l"(a), "l"(b), "l"(c));
    return d;
}

#define CP_ASYNC16(sdst, gsrc)                                                \
    asm volatile("cp.async.cg.shared.global [%0], [%1], 16;"                  \
                 :: "r"(sdst), "l"(gsrc))
#define CP_COMMIT() asm volatile("cp.async.commit_group;")
#define CP_WAIT1()  asm volatile("cp.async.wait_group 1;")

__device__ __forceinline__ void prefetch_kv(const float* __restrict__ gsrc,
                                            float* sdst) {
    #pragma unroll 2
    for (int j = threadIdx.x; j < NKEY * 16; j += TPB) {
        int row = j >> 4;
        int c4  = j & 15;
        unsigned sa =
            (unsigned)__cvta_generic_to_shared(sdst + row * STR + c4 * 4);
        CP_ASYNC16(sa, gsrc + j * 4);
    }
}

__global__ void __launch_bounds__(TPB, 1)
raamh_kernel(const float* __restrict__ q_x, const float* __restrict__ kv_x,
             const float* __restrict__ Wk,  const float* __restrict__ Wq,
             const float* __restrict__ Wv,  const float* __restrict__ bias,
             const float* __restrict__ Ws,  const float* __restrict__ bs,
             float* __restrict__ out, int BT)
{
    extern __shared__ float smem[];
    float* s_kv[2] = { smem + OFF_KV0, smem + OFF_KV1 };
    float* s_wk   = smem + OFF_WK;
    float* s_qb   = smem + OFF_QB;
    float* s_q    = smem + OFF_Q;
    float* s_ws   = smem + OFF_WS;
    float* s_bias = smem + OFF_BIAS;
    float* s_sc   = smem + OFF_SC;
    float* s_w    = smem + OFF_W;     // [n][4] heads, n-major
    float* s_wv   = smem + OFF_WV;
    float* s_part = smem + OFF_PART;
    float* s_bs   = smem + OFF_BS;

    const int tid  = threadIdx.x;
    const int lane = tid & 31;
    const int wrp  = tid >> 5;
    const int h    = tid >> 6;

    // ---- one-time staging ----
    {
        const float4* wk4 = (const float4*)Wk;
        #pragma unroll 4
        for (int j = tid; j < DOUT * 16; j += TPB) {
            int row = j >> 4, c4 = j & 15;
            float4 v = wk4[j];
            *(float4*)(s_wk + row * STR + c4 * 4) = v;
        }
        if (tid < DK) {
            s_ws[tid]   = Ws[tid];
            s_bias[tid] = bias[tid];
        }
        if (tid == 0) s_bs[0] = bs[0];
        if (tid < 128) {  // zero garbage row 127 of both kv buffers
            s_kv[tid >> 6][127 * STR + (tid & 63)] = 0.f;
        }
    }

    int bt0 = blockIdx.x;
    int buf = 0;
    prefetch_kv(kv_x + (size_t)bt0 * (NKEY * DK), s_kv[0]);
    CP_COMMIT();

    for (int bt = bt0; bt < BT; bt += gridDim.x) {
        if (tid < DK) s_q[tid] = q_x[bt * DK + tid];

        int bt_next = bt + gridDim.x;
        if (bt_next < BT)
            prefetch_kv(kv_x + (size_t)bt_next * (NKEY * DK), s_kv[buf ^ 1]);
        CP_COMMIT();
        CP_WAIT1();
        __syncthreads();

        const float* kvb = s_kv[buf];

        // ---- q projection + bias ----
        {
            const float4* wq4 = (const float4*)(Wq + tid * DK);
            float a0 = 0.f, a1 = 0.f, a2 = 0.f, a3 = 0.f;
            #pragma unroll
            for (int i = 0; i < 16; i++) {
                float4 w = __ldg(wq4 + i);
                a0 = fmaf(s_q[4 * i + 0], w.x, a0);
                a1 = fmaf(s_q[4 * i + 1], w.y, a1);
                a2 = fmaf(s_q[4 * i + 2], w.z, a2);
                a3 = fmaf(s_q[4 * i + 3], w.w, a3);
            }
            s_qb[tid] = (a0 + a1) + (a2 + a3) + s_bias[tid & (DK - 1)];
        }
        __syncthreads();

        const float bsv = s_bs[0];

        // ---- score GEMM: warp tile = 8 n (broadcast) x 128 o ----
        // o = ohalf*128 + oi*32 + lane ; head = ohalf*2 + (oi>>1)
        #pragma unroll 1
        for (int it = 0; it < 4; ++it) {
            const int t     = it * 8 + wrp;   // 0..31
            const int ohalf = t >> 4;         // 0/1
            const int nb8   = t & 15;         // 8-n block
            const float* kvp = kvb + nb8 * 8 * STR;           // warp-uniform
            const float* wkp = s_wk + (ohalf * 128 + lane) * STR;

            unsigned long long acc[8][4];
            #pragma unroll
            for (int j = 0; j < 8; ++j)
                #pragma unroll
                for (int oi = 0; oi < 4; ++oi) acc[j][oi] = 0ull;

            #pragma unroll 2
            for (int kk = 0; kk < DK; kk += 4) {
                ulonglong2 kvv[8];              // broadcast loads
                #pragma unroll
                for (int j = 0; j < 8; ++j)
                    kvv[j] = *(const ulonglong2*)(kvp + j * STR + kk);
                #pragma unroll
                for (int oi = 0; oi < 4; ++oi) {
                    ulonglong2 w =
                        *(const ulonglong2*)(wkp + oi * 32 * STR + kk);
                    #pragma unroll
                    for (int j = 0; j < 8; ++j) {
                        acc[j][oi] = fma2(kvv[j].x, w.x, acc[j][oi]);
                        acc[j][oi] = fma2(kvv[j].y, w.y, acc[j][oi]);
                    }
                }
            }

            // epilogue: tanh + Ws weighting, per (n, head) partials
            float part[8][2];
            #pragma unroll
            for (int j = 0; j < 8; ++j) { part[j][0] = 0.f; part[j][1] = 0.f; }

            #pragma unroll
            for (int oi = 0; oi < 4; ++oi) {
                const int hh = oi >> 1;
                const int k  = (oi & 1) * 32 + lane;   // k within head
                const float wsk = s_ws[k];
                const float qbo = s_qb[(ohalf * 2 + hh) * 64 + k];
                #pragma unroll
                for (int j = 0; j < 8; ++j) {
                    float lo, hi;
                    asm("mov.b64 {%0, %1}, %2;"
                        : "=f"(lo), "=f"(hi) : "l"(acc[j][oi]));
                    part[j][hh] =
                        fmaf(wsk, tanh_fast(lo + hi + qbo), part[j][hh]);
                }
            }
            // full-warp butterfly: 16 independent sums
            #pragma unroll
            for (int m = 1; m < 32; m <<= 1)
                #pragma unroll
                for (int j = 0; j < 8; ++j) {
                    part[j][0] += __shfl_xor_sync(0xffffffffu, part[j][0], m);
                    part[j][1] += __shfl_xor_sync(0xffffffffu, part[j][1], m);
                }
            if (lane < 16) {
                const int j  = lane & 7;
                const int hh = lane >> 3;
                s_sc[(ohalf * 2 + hh) * 128 + nb8 * 8 + j] =
                    part[j][hh] + bsv;
            }
        }
        __syncthreads();

        // ---- softmax per head (one warp per head), n-major s_w ----
        if (tid < NH * 32) {
            int hh = tid >> 5;
            int ln = tid & 31;
            const float* sc = s_sc + hh * 128;
            float v0 = sc[ln];
            float v1 = sc[ln + 32];
            float v2 = sc[ln + 64];
            float v3 = (ln + 96 < NKEY) ? sc[ln + 96] : -1e30f;
            float m = fmaxf(fmaxf(v0, v1), fmaxf(v2, v3));
            #pragma unroll
            for (int o = 16; o > 0; o >>= 1)
                m = fmaxf(m, __shfl_xor_sync(0xffffffffu, m, o));
            float e0 = __expf(v0 - m);
            float e1 = __expf(v1 - m);
            float e2 = __expf(v2 - m);
            float e3 = (ln + 96 < NKEY) ? __expf(v3 - m) : 0.f;
            float s = (e0 + e1) + (e2 + e3);
            #pragma unroll
            for (int o = 16; o > 0; o >>= 1)
                s += __shfl_xor_sync(0xffffffffu, s, o);
            float inv = 1.f / s;
            s_w[ln * 4 + hh]        = e0 * inv;
            s_w[(ln + 32) * 4 + hh] = e1 * inv;
            s_w[(ln + 64) * 4 + hh] = e2 * inv;
            if (ln + 96 < NKEY) s_w[(ln + 96) * 4 + hh] = e3 * inv;
        }
        __syncthreads();

        // ---- weighted kv sum, quarter-split over n ----
        {
            const int q4 = tid >> 6;
            const int i  = tid & 63;
            float a0 = 0.f, a1 = 0.f, a2 = 0.f, a3 = 0.f;
            const int n0 = q4 * 32;
            const int n1 = (q4 == 3) ? NKEY : n0 + 32;
            #pragma unroll 4
            for (int n = n0; n < n1; ++n) {
                float  v  = kvb[n * STR + i];
                float4 w4 = *(const float4*)(s_w + n * 4);
                a0 = fmaf(w4.x, v, a0);
                a1 = fmaf(w4.y, v, a1);
                a2 = fmaf(w4.z, v, a2);
                a3 = fmaf(w4.w, v, a3);
            }
            s_part[(0 * 64 + i) * 4 + q4] = a0;
            s_part[(1 * 64 + i) * 4 + q4] = a1;
            s_part[(2 * 64 + i) * 4 + q4] = a2;
            s_part[(3 * 64 + i) * 4 + q4] = a3;
        }
        __syncthreads();
        {
            float4 p = *(const float4*)(s_part + tid * 4);
            s_wv[tid] = (p.x + p.y) + (p.z + p.w);
        }
        __syncthreads();

        // ---- output projection ----
        {
            const float* wvh = s_wv + (h << 6);
            const float4* wv4 = (const float4*)(Wv + tid * DK);
            float a0 = 0.f, a1 = 0.f, a2 = 0.f, a3 = 0.f;
            #pragma unroll
            for (int i = 0; i < 16; i++) {
                float4 w = __ldg(wv4 + i);
                a0 = fmaf(wvh[4 * i + 0], w.x, a0);
                a1 = fmaf(wvh[4 * i + 1], w.y, a1);
                a2 = fmaf(wvh[4 * i + 2], w.z, a2);
                a3 = fmaf(wvh[4 * i + 3], w.w, a3);
            }
            out[(size_t)bt * DOUT + tid] = (a0 + a1) + (a2 + a3);
        }

        buf ^= 1;
    }
}

extern "C" void kernel_launch(void* const* d_in, const int* in_sizes, int n_in,
                              void* d_out, int out_size) {
    (void)n_in; (void)out_size;
    const float* q_x  = (const float*)d_in[0];
    const float* kv_x = (const float*)d_in[1];
    const float* Wk   = (const float*)d_in[2];
    const float* Wq   = (const float*)d_in[3];
    const float* Wv   = (const float*)d_in[4];
    const float* bias = (const float*)d_in[5];
    const float* Ws   = (const float*)d_in[6];
    const float* bs   = (const float*)d_in[7];
    float* out = (float*)d_out;

    const int BT = in_sizes[0] / DK;
    int grid = BT < 152 ? BT : 152;

    cudaFuncSetAttribute(raamh_kernel,
                         cudaFuncAttributeMaxDynamicSharedMemorySize,
                         SMEM_BYTES);
    raamh_kernel<<<grid, TPB, SMEM_BYTES>>>(q_x, kv_x, Wk, Wq, Wv,
                                            bias, Ws, bs, out, BT);
}

// round 6
// speedup vs baseline: 4.1974x; 2.2705x over previous
#include <cuda_runtime.h>
#include <cstdint>
#include <cstddef>

#define TPB   256
#define NKEY  127
#define NH    4
#define DK    64
#define DOUT  256
#define STR   68   // padded row stride (floats)

static constexpr int KV_FLOATS = 128 * STR;
static constexpr int WK_FLOATS = DOUT * STR;
static constexpr int OFF_KV0  = 0;
static constexpr int OFF_KV1  = OFF_KV0 + KV_FLOATS;
static constexpr int OFF_WK   = OFF_KV1 + KV_FLOATS;
static constexpr int OFF_QB   = OFF_WK + WK_FLOATS;
static constexpr int OFF_Q    = OFF_QB + DOUT;
static constexpr int OFF_WS   = OFF_Q + DK;
static constexpr int OFF_BIAS = OFF_WS + DK;
static constexpr int OFF_SC   = OFF_BIAS + DK;          // [4][128]
static constexpr int OFF_W    = OFF_SC + NH * 128;      // [128][4] n-major
static constexpr int OFF_WV   = OFF_W + 128 * NH;       // [256]
static constexpr int OFF_PART = OFF_WV + DOUT;          // [256][4]
static constexpr int OFF_BS   = OFF_PART + DOUT * 4;
static constexpr int SMEM_FLOATS = OFF_BS + 4;
static constexpr int SMEM_BYTES  = SMEM_FLOATS * 4;

__device__ __forceinline__ float tanh_fast(float x) {
    float y;
    asm("tanh.approx.f32 %0, %1;" : "=f"(y) : "f"(x));
    return y;
}

// m16n8k8 tf32 MMA, row(A) x col(B), fp32 accumulate (arch-neutral PTX)
__device__ __forceinline__ void mma8(float& d0, float& d1, float& d2, float& d3,
                                     float a0, float a1, float a2, float a3,
                                     float b0, float b1) {
    asm volatile(
        "mma.sync.aligned.m16n8k8.row.col.f32.tf32.tf32.f32 "
        "{%0,%1,%2,%3}, {%4,%5,%6,%7}, {%8,%9}, {%0,%1,%2,%3};"
        : "+f"(d0), "+f"(d1), "+f"(d2), "+f"(d3)
        : "r"(__float_as_uint(a0)), "r"(__float_as_uint(a1)),
          "r"(__float_as_uint(a2)), "r"(__float_as_uint(a3)),
          "r"(__float_as_uint(b0)), "r"(__float_as_uint(b1)));
}

#define CP_ASYNC16(sdst, gsrc)                                                \
    asm volatile("cp.async.cg.shared.global [%0], [%1], 16;"                  \
                 :: "r"(sdst), "l"(gsrc))
#define CP_COMMIT() asm volatile("cp.async.commit_group;")
#define CP_WAIT1()  asm volatile("cp.async.wait_group 1;")

__device__ __forceinline__ void prefetch_kv(const float* __restrict__ gsrc,
                                            float* sdst) {
    #pragma unroll 2
    for (int j = threadIdx.x; j < NKEY * 16; j += TPB) {
        int row = j >> 4;
        int c4  = j & 15;
        unsigned sa =
            (unsigned)__cvta_generic_to_shared(sdst + row * STR + c4 * 4);
        CP_ASYNC16(sa, gsrc + j * 4);
    }
}

__global__ void __launch_bounds__(TPB, 1)
raamh_kernel(const float* __restrict__ q_x, const float* __restrict__ kv_x,
             const float* __restrict__ Wk,  const float* __restrict__ Wq,
             const float* __restrict__ Wv,  const float* __restrict__ bias,
             const float* __restrict__ Ws,  const float* __restrict__ bs,
             float* __restrict__ out, int BT)
{
    extern __shared__ float smem[];
    float* s_kv[2] = { smem + OFF_KV0, smem + OFF_KV1 };
    float* s_wk   = smem + OFF_WK;
    float* s_qb   = smem + OFF_QB;
    float* s_q    = smem + OFF_Q;
    float* s_ws   = smem + OFF_WS;
    float* s_bias = smem + OFF_BIAS;
    float* s_sc   = smem + OFF_SC;
    float* s_w    = smem + OFF_W;     // [n][4] heads, n-major
    float* s_wv   = smem + OFF_WV;
    float* s_part = smem + OFF_PART;
    float* s_bs   = smem + OFF_BS;

    const int tid  = threadIdx.x;
    const int lane = tid & 31;
    const int wrp  = tid >> 5;
    const int h    = tid >> 6;
    const int g    = lane >> 2;       // groupID (fragment row)
    const int tg   = lane & 3;        // thread-in-group (fragment col)
    const int wm   = wrp & 3;         // warp row-block (32 n each)
    const int wn   = wrp >> 2;        // warp head-within-half

    // ---- one-time staging ----
    {
        const float4* wk4 = (const float4*)Wk;
        #pragma unroll 4
        for (int j = tid; j < DOUT * 16; j += TPB) {
            int row = j >> 4, c4 = j & 15;
            float4 v = wk4[j];
            *(float4*)(s_wk + row * STR + c4 * 4) = v;
        }
        if (tid < DK) {
            s_ws[tid]   = Ws[tid];
            s_bias[tid] = bias[tid];
        }
        if (tid == 0) s_bs[0] = bs[0];
        if (tid < 128) {  // zero garbage row 127 of both kv buffers
            s_kv[tid >> 6][127 * STR + (tid & 63)] = 0.f;
        }
    }

    int bt0 = blockIdx.x;
    int buf = 0;
    prefetch_kv(kv_x + (size_t)bt0 * (NKEY * DK), s_kv[0]);
    CP_COMMIT();

    for (int bt = bt0; bt < BT; bt += gridDim.x) {
        if (tid < DK) s_q[tid] = q_x[bt * DK + tid];

        int bt_next = bt + gridDim.x;
        if (bt_next < BT)
            prefetch_kv(kv_x + (size_t)bt_next * (NKEY * DK), s_kv[buf ^ 1]);
        CP_COMMIT();
        CP_WAIT1();
        __syncthreads();

        const float* kvb = s_kv[buf];

        // ---- q projection + bias ----
        {
            const float4* wq4 = (const float4*)(Wq + tid * DK);
            float a0 = 0.f, a1 = 0.f, a2 = 0.f, a3 = 0.f;
            #pragma unroll
            for (int i = 0; i < 16; i++) {
                float4 w = __ldg(wq4 + i);
                a0 = fmaf(s_q[4 * i + 0], w.x, a0);
                a1 = fmaf(s_q[4 * i + 1], w.y, a1);
                a2 = fmaf(s_q[4 * i + 2], w.z, a2);
                a3 = fmaf(s_q[4 * i + 3], w.w, a3);
            }
            s_qb[tid] = (a0 + a1) + (a2 + a3) + s_bias[tid & (DK - 1)];
        }
        __syncthreads();

        const float bsv = s_bs[0];

        // ---- score GEMM via tensor cores (tf32 mma.sync) ----
        // per o-half: warp tile = 32 n-rows (2 m16 blocks) x 64 o (full head)
        #pragma unroll 1
        for (int half = 0; half < 2; ++half) {
            const int head = half * 2 + wn;
            const float* kvp = kvb + (wm * 32) * STR;
            const float* wkp = s_wk + (head * 64) * STR;

            float acc[2][8][4];
            #pragma unroll
            for (int mb = 0; mb < 2; ++mb)
                #pragma unroll
                for (int nb = 0; nb < 8; ++nb)
                    #pragma unroll
                    for (int c = 0; c < 4; ++c) acc[mb][nb][c] = 0.f;

            #pragma unroll
            for (int kb = 0; kb < 8; ++kb) {
                const int k0 = kb * 8;
                float a[2][4];
                #pragma unroll
                for (int mb = 0; mb < 2; ++mb) {
                    const float* ar = kvp + (mb * 16 + g) * STR + k0 + tg;
                    a[mb][0] = ar[0];
                    a[mb][1] = ar[8 * STR];
                    a[mb][2] = ar[4];
                    a[mb][3] = ar[8 * STR + 4];
                }
                float b[8][2];
                #pragma unroll
                for (int nb = 0; nb < 8; ++nb) {
                    const float* br = wkp + (nb * 8 + g) * STR + k0 + tg;
                    b[nb][0] = br[0];
                    b[nb][1] = br[4];
                }
                #pragma unroll
                for (int mb = 0; mb < 2; ++mb)
                    #pragma unroll
                    for (int nb = 0; nb < 8; ++nb)
                        mma8(acc[mb][nb][0], acc[mb][nb][1],
                             acc[mb][nb][2], acc[mb][nb][3],
                             a[mb][0], a[mb][1], a[mb][2], a[mb][3],
                             b[nb][0], b[nb][1]);
            }

            // epilogue: tanh + Ws reduction over the 64 o of this head
            float part[2][2];
            part[0][0] = part[0][1] = part[1][0] = part[1][1] = 0.f;
            #pragma unroll
            for (int nb = 0; nb < 8; ++nb) {
                #pragma unroll
                for (int cc = 0; cc < 2; ++cc) {
                    const int k = nb * 8 + tg * 2 + cc;   // col within head
                    const float wsk = s_ws[k];
                    const float qbo = s_qb[head * 64 + k];
                    #pragma unroll
                    for (int mb = 0; mb < 2; ++mb) {
                        part[mb][0] = fmaf(
                            wsk, tanh_fast(acc[mb][nb][cc] + qbo),
                            part[mb][0]);
                        part[mb][1] = fmaf(
                            wsk, tanh_fast(acc[mb][nb][2 + cc] + qbo),
                            part[mb][1]);
                    }
                }
            }
            // butterfly over tg lanes (xor 1, 2)
            #pragma unroll
            for (int m = 1; m <= 2; m <<= 1) {
                #pragma unroll
                for (int mb = 0; mb < 2; ++mb) {
                    part[mb][0] += __shfl_xor_sync(0xffffffffu, part[mb][0], m);
                    part[mb][1] += __shfl_xor_sync(0xffffffffu, part[mb][1], m);
                }
            }
            if (tg == 0) {
                #pragma unroll
                for (int mb = 0; mb < 2; ++mb) {
                    const int r = wm * 32 + mb * 16 + g;
                    s_sc[head * 128 + r]     = part[mb][0] + bsv;
                    s_sc[head * 128 + r + 8] = part[mb][1] + bsv;
                }
            }
        }
        __syncthreads();

        // ---- softmax per head (one warp per head), n-major s_w ----
        if (tid < NH * 32) {
            int hh = tid >> 5;
            int ln = tid & 31;
            const float* sc = s_sc + hh * 128;
            float v0 = sc[ln];
            float v1 = sc[ln + 32];
            float v2 = sc[ln + 64];
            float v3 = (ln + 96 < NKEY) ? sc[ln + 96] : -1e30f;
            float m = fmaxf(fmaxf(v0, v1), fmaxf(v2, v3));
            #pragma unroll
            for (int o = 16; o > 0; o >>= 1)
                m = fmaxf(m, __shfl_xor_sync(0xffffffffu, m, o));
            float e0 = __expf(v0 - m);
            float e1 = __expf(v1 - m);
            float e2 = __expf(v2 - m);
            float e3 = (ln + 96 < NKEY) ? __expf(v3 - m) : 0.f;
            float s = (e0 + e1) + (e2 + e3);
            #pragma unroll
            for (int o = 16; o > 0; o >>= 1)
                s += __shfl_xor_sync(0xffffffffu, s, o);
            float inv = 1.f / s;
            s_w[ln * 4 + hh]        = e0 * inv;
            s_w[(ln + 32) * 4 + hh] = e1 * inv;
            s_w[(ln + 64) * 4 + hh] = e2 * inv;
            if (ln + 96 < NKEY) s_w[(ln + 96) * 4 + hh] = e3 * inv;
        }
        __syncthreads();

        // ---- weighted kv sum, quarter-split over n ----
        {
            const int q4 = tid >> 6;
            const int i  = tid & 63;
            float a0 = 0.f, a1 = 0.f, a2 = 0.f, a3 = 0.f;
            const int n0 = q4 * 32;
            const int n1 = (q4 == 3) ? NKEY : n0 + 32;
            #pragma unroll 4
            for (int n = n0; n < n1; ++n) {
                float  v  = kvb[n * STR + i];
                float4 w4 = *(const float4*)(s_w + n * 4);
                a0 = fmaf(w4.x, v, a0);
                a1 = fmaf(w4.y, v, a1);
                a2 = fmaf(w4.z, v, a2);
                a3 = fmaf(w4.w, v, a3);
            }
            s_part[(0 * 64 + i) * 4 + q4] = a0;
            s_part[(1 * 64 + i) * 4 + q4] = a1;
            s_part[(2 * 64 + i) * 4 + q4] = a2;
            s_part[(3 * 64 + i) * 4 + q4] = a3;
        }
        __syncthreads();
        {
            float4 p = *(const float4*)(s_part + tid * 4);
            s_wv[tid] = (p.x + p.y) + (p.z + p.w);
        }
        __syncthreads();

        // ---- output projection ----
        {
            const float* wvh = s_wv + (h << 6);
            const float4* wv4 = (const float4*)(Wv + tid * DK);
            float a0 = 0.f, a1 = 0.f, a2 = 0.f, a3 = 0.f;
            #pragma unroll
            for (int i = 0; i < 16; i++) {
                float4 w = __ldg(wv4 + i);
                a0 = fmaf(wvh[4 * i + 0], w.x, a0);
                a1 = fmaf(wvh[4 * i + 1], w.y, a1);
                a2 = fmaf(wvh[4 * i + 2], w.z, a2);
                a3 = fmaf(wvh[4 * i + 3], w.w, a3);
            }
            out[(size_t)bt * DOUT + tid] = (a0 + a1) + (a2 + a3);
        }

        buf ^= 1;
    }
}

extern "C" void kernel_launch(void* const* d_in, const int* in_sizes, int n_in,
                              void* d_out, int out_size) {
    (void)n_in; (void)out_size;
    const float* q_x  = (const float*)d_in[0];
    const float* kv_x = (const float*)d_in[1];
    const float* Wk   = (const float*)d_in[2];
    const float* Wq   = (const float*)d_in[3];
    const float* Wv   = (const float*)d_in[4];
    const float* bias = (const float*)d_in[5];
    const float* Ws   = (const float*)d_in[6];
    const float* bs   = (const float*)d_in[7];
    float* out = (float*)d_out;

    const int BT = in_sizes[0] / DK;
    int grid = BT < 152 ? BT : 152;

    cudaFuncSetAttribute(raamh_kernel,
                         cudaFuncAttributeMaxDynamicSharedMemorySize,
                         SMEM_BYTES);
    raamh_kernel<<<grid, TPB, SMEM_BYTES>>>(q_x, kv_x, Wk, Wq, Wv,
                                            bias, Ws, bs, out, BT);
}